// round 16
// baseline (speedup 1.0000x reference)
#include <cuda_runtime.h>
#include <cuda_fp16.h>
#include <mma.h>
using namespace nvcuda;

#define V 8192
#define E 262144
#define D 128
#define SLOTS 128           // hash slots per row (power of 2)
#define GB 256              // gemm grid: V / 32 rows per block
#define RPB 4               // rows per k_row block (2 warps per row)

// padded smem strides (bank-conflict-free for LDSM: stride mod 128B == 16B)
#define WS 136              // half stride for W/A tiles  (272 B)
#define CS 132              // float stride for C tile    (528 B)

// dynamic smem: Whi+Wlo (2*128*136*2) + Ahi+Alo (2*32*136*2) + C (32*132*4)
#define GEMM_SMEM_BYTES (2*128*WS*2 + 2*32*WS*2 + 32*CS*4)

// ---------------- scratch (device globals; no allocations allowed) ----------
__device__ __half             g_hwh[V * D];      // hw in fp16 (2 MB, L2-resident)
__device__ __half             g_Whi[D * D];      // W hi split (pre-converted once)
__device__ __half             g_Wlo[D * D];      // W lo split
__device__ float              g_s1[V];           // hw[v] . att[:128]  (exact fp32)
__device__ float              g_s2[V];           // hw[v] . att[128:]
__device__ float              g_Spart[GB * D];   // per-block colsum partials
__device__ float              g_S[D];            // reduced colsum of hw
__device__ unsigned           g_ew32[(size_t)V * SLOTS]; // (idx+1)<<13 | dst
__device__ int                g_is64;            // edge_index dtype flag

// =================== K0: W fp16-split (once) + dtype detection ===============
__global__ void k_prep(const float* __restrict__ Wm, const int* __restrict__ e32) {
    int tid = threadIdx.x;
    if (blockIdx.x == 0) {
        __shared__ int flag;
        if (tid == 0) flag = 0;
        __syncthreads();
        if (e32[2 * tid + 1] != 0) atomicExch(&flag, 1);
        __syncthreads();
        if (tid == 0) g_is64 = (flag == 0) ? 1 : 0;
    }
    int i4 = blockIdx.x * 256 + tid;              // 0..4095
    float4 v = ((const float4*)Wm)[i4];
    __half hx = __float2half_rn(v.x), hy = __float2half_rn(v.y);
    __half hz = __float2half_rn(v.z), hw_ = __float2half_rn(v.w);
    __half2 ph0 = __halves2half2(hx, hy), ph1 = __halves2half2(hz, hw_);
    __half lx = __float2half_rn(v.x - __half2float(hx));
    __half ly = __float2half_rn(v.y - __half2float(hy));
    __half lz = __float2half_rn(v.z - __half2float(hz));
    __half lw = __float2half_rn(v.w - __half2float(hw_));
    __half2 pl0 = __halves2half2(lx, ly), pl1 = __halves2half2(lz, lw);
    uint2 uh, ul;
    uh.x = *(unsigned*)&ph0; uh.y = *(unsigned*)&ph1;
    ul.x = *(unsigned*)&pl0; ul.y = *(unsigned*)&pl1;
    *(uint2*)(g_Whi + (size_t)i4 * 4) = uh;
    *(uint2*)(g_Wlo + (size_t)i4 * 4) = ul;
}

// =================== K1: tensor-core GEMM hw = h @ W^T (fp16-split, smem) ====
__global__ void __launch_bounds__(256) k_gemm(const float* __restrict__ h,
                                              const float* __restrict__ att) {
    extern __shared__ char dynsmem[];
    __half* sWhi = (__half*)dynsmem;              // [128][WS]  W[col][k]
    __half* sWlo = sWhi + 128 * WS;
    __half* sAhi = sWlo + 128 * WS;               // [32][WS]
    __half* sAlo = sAhi + 32 * WS;
    float*  sC   = (float*)(sAlo + 32 * WS);      // [32][CS] fp32 result

    int tid = threadIdx.x;
    int warpId = tid >> 5, lane = tid & 31;
    int row0 = blockIdx.x * 32;

    // ---- copy pre-split W into padded smem: 2048 uint4 per array, 8/thread
    const uint4* Wh4 = (const uint4*)g_Whi;
    const uint4* Wl4 = (const uint4*)g_Wlo;
#pragma unroll
    for (int j = 0; j < 8; j++) {
        int i = tid + j * 256;                    // 0..2047
        int row = i >> 4, c8 = (i & 15) * 8;
        *(uint4*)(sWhi + row * WS + c8) = Wh4[i];
        *(uint4*)(sWlo + row * WS + c8) = Wl4[i];
    }
    // ---- convert A (32 rows x 128 = 1024 float4): 4 per thread ----
#pragma unroll
    for (int j = 0; j < 4; j++) {
        int i4 = tid + j * 256;
        int row = i4 >> 5, c4 = (i4 & 31) * 4;
        float4 v = *(const float4*)(h + (size_t)row0 * D + (size_t)i4 * 4);
        __half hx = __float2half_rn(v.x), hy = __float2half_rn(v.y);
        __half hz = __float2half_rn(v.z), hw_ = __float2half_rn(v.w);
        __half2 ph0 = __halves2half2(hx, hy), ph1 = __halves2half2(hz, hw_);
        __half lx = __float2half_rn(v.x - __half2float(hx));
        __half ly = __float2half_rn(v.y - __half2float(hy));
        __half lz = __float2half_rn(v.z - __half2float(hz));
        __half lw = __float2half_rn(v.w - __half2float(hw_));
        __half2 pl0 = __halves2half2(lx, ly), pl1 = __halves2half2(lz, lw);
        uint2 uh, ul;
        uh.x = *(unsigned*)&ph0; uh.y = *(unsigned*)&ph1;
        ul.x = *(unsigned*)&pl0; ul.y = *(unsigned*)&pl1;
        *(uint2*)(sAhi + row * WS + c4) = uh;
        *(uint2*)(sAlo + row * WS + c4) = ul;
    }
    __syncthreads();

    // ---- wmma: warp w -> col-tile w; row-tiles 0,1 ----
    int ct = warpId;
#pragma unroll
    for (int rt = 0; rt < 2; rt++) {
        wmma::fragment<wmma::accumulator, 16, 16, 16, float> acc;
        wmma::fill_fragment(acc, 0.f);
#pragma unroll
        for (int k0 = 0; k0 < 8; k0++) {
            wmma::fragment<wmma::matrix_a, 16, 16, 16, __half, wmma::row_major> ahi, alo;
            wmma::load_matrix_sync(ahi, sAhi + rt * 16 * WS + k0 * 16, WS);
            wmma::load_matrix_sync(alo, sAlo + rt * 16 * WS + k0 * 16, WS);
            wmma::fragment<wmma::matrix_b, 16, 16, 16, __half, wmma::col_major> bhi, blo;
            wmma::load_matrix_sync(bhi, sWhi + ct * 16 * WS + k0 * 16, WS);
            wmma::load_matrix_sync(blo, sWlo + ct * 16 * WS + k0 * 16, WS);
            wmma::mma_sync(acc, ahi, bhi, acc);
            wmma::mma_sync(acc, ahi, blo, acc);
            wmma::mma_sync(acc, alo, bhi, acc);
        }
        wmma::store_matrix_sync(sC + rt * 16 * CS + ct * 16, acc, CS, wmma::mem_row_major);
    }
    __syncthreads();

    // ---- epilogue (all from fp32 sC) ----
#pragma unroll
    for (int j = 0; j < 4; j++) {
        int i4 = tid + j * 256;
        int row = i4 >> 5, off = (i4 & 31) * 4;
        float4 v = *(const float4*)(sC + row * CS + off);
        __half2 q0 = __floats2half2_rn(v.x, v.y);
        __half2 q1 = __floats2half2_rn(v.z, v.w);
        uint2 u;
        u.x = *(unsigned*)&q0; u.y = *(unsigned*)&q1;
        *(uint2*)(g_hwh + (size_t)(row0 + row) * D + off) = u;
    }
    // s1/s2: warp w owns rows 4w..4w+3; lane dots 4 cols, shfl-reduce (exact fp32)
    {
        float4 a1 = *(const float4*)(att + lane * 4);
        float4 a2 = *(const float4*)(att + D + lane * 4);
#pragma unroll
        for (int r = 0; r < 4; r++) {
            int row = warpId * 4 + r;
            float4 cv = *(const float4*)(sC + row * CS + lane * 4);
            float s1 = cv.x * a1.x + cv.y * a1.y + cv.z * a1.z + cv.w * a1.w;
            float s2 = cv.x * a2.x + cv.y * a2.y + cv.z * a2.z + cv.w * a2.w;
#pragma unroll
            for (int o = 16; o; o >>= 1) {
                s1 += __shfl_xor_sync(0xffffffffu, s1, o);
                s2 += __shfl_xor_sync(0xffffffffu, s2, o);
            }
            if (lane == 0) { g_s1[row0 + row] = s1; g_s2[row0 + row] = s2; }
        }
    }
    // colsum partial: threads 0..127, column tid over 32 rows (conflict-free)
    if (tid < D) {
        float s = 0.f;
#pragma unroll 8
        for (int r = 0; r < 32; r++) s += sC[r * CS + tid];
        g_Spart[blockIdx.x * D + tid] = s;
    }
}

// =================== K2: hash insert only (32-bit; dedup by atomicMax) =======
// Record: bits[0:13)=dst, [13:32)=edge_idx+1. Max idx wins = last-write-wins.
__global__ void k_scatter(const int* __restrict__ e32) {
    // block 0: reduce colsum partials -> g_S (k_row reads it later)
    if (blockIdx.x == 0 && threadIdx.x < D) {
        float s = 0.f;
#pragma unroll 16
        for (int b = 0; b < GB; b++) s += g_Spart[b * D + threadIdx.x];
        g_S[threadIdx.x] = s;
    }
    int e = blockIdx.x * blockDim.x + threadIdx.x;
    if (e >= E) return;
    int src, dst;
    if (g_is64) {
        src = ((const int2*)e32)[e].x;
        dst = ((const int2*)e32)[E + e].x;
    } else {
        src = e32[e];
        dst = e32[E + e];
    }
    unsigned rec = ((unsigned)(e + 1) << 13) | (unsigned)dst;
    unsigned slot = ((unsigned)dst * 2654435761u) >> 25;   // 7-bit hash
    unsigned* tab = g_ew32 + (size_t)src * SLOTS;
    for (int probe = 0; probe < SLOTS; probe++) {
        unsigned old = atomicCAS(&tab[slot], 0u, rec);
        if (old == 0u) break;                              // claimed empty slot
        if ((old & 0x1FFFu) == (unsigned)dst) {
            atomicMax(&tab[slot], rec);                    // last-write-wins
            break;
        }
        slot = (slot + 1) & (SLOTS - 1);
    }
}

// =================== K3: 2 warps/row: scan half-slots + gather + combine =====
__global__ void __launch_bounds__(256, 4) k_row(float* __restrict__ out) {
    __shared__ uint2 sm[RPB][SLOTS];     // {dst, float bits of w}; [sub*64..] halves
    __shared__ float sacc[RPB][D];       // sub-1 staging
    __shared__ float sdsum[RPB][2];
    int wid = threadIdx.x >> 5, lane = threadIdx.x & 31;
    int r = wid >> 1, sub = wid & 1;
    int row = blockIdx.x * RPB + r;
    unsigned* tab = g_ew32 + (size_t)row * SLOTS + sub * 64;
    float s1row = g_s1[row];

    // ---- scan own 64 slots, re-zero, compact + recompute weight ----
    float dsum = 0.f;
    int cnt = 0;
#pragma unroll
    for (int rnd = 0; rnd < 2; rnd++) {
        int s = rnd * 32 + lane;
        unsigned v = tab[s];
        tab[s] = 0u;                                     // replay-safe re-zero
        unsigned mask = __ballot_sync(0xffffffffu, v != 0u);
        if (v != 0u) {
            int pos = cnt + __popc(mask & ((1u << lane) - 1u));
            unsigned dst = v & 0x1FFFu;
            float a = s1row + g_s2[dst];
            a = a > 0.f ? a : 0.2f * a;                  // LeakyReLU(0.2)
            float w = expm1f(a);                         // exp(a) - 1 (fp32)
            sm[r][sub * 64 + pos] = make_uint2(dst, __float_as_uint(w));
            dsum += w;
        }
        cnt += __popc(mask);
    }
    int dpad = (cnt + 7) & ~7;
    for (int t = cnt + lane; t < dpad; t += 32)
        sm[r][sub * 64 + t] = make_uint2(0u, 0u);        // harmless pad (w=0)
    __syncwarp();

    // ---- pipelined pair-gather over own segment ----
    float acc[8];
#pragma unroll
    for (int i = 0; i < 8; i++) acc[i] = 0.f;
    int half_ = lane >> 4;
    int cl = (lane & 15) * 8;
    const __half* hw = g_hwh;
    const uint2* seg = &sm[r][sub * 64];

    uint2 mcur[4]; uint4 vcur[4];
    if (dpad > 0) {
#pragma unroll
        for (int p = 0; p < 4; p++) {
            mcur[p] = seg[2 * p + half_];
            vcur[p] = *(const uint4*)(hw + (size_t)mcur[p].x * D + cl);
        }
    }
    for (int t = 0; t < dpad; t += 8) {
        uint2 mn[4]; uint4 vn[4];
        bool more = (t + 8 < dpad);
        if (more) {
#pragma unroll
            for (int p = 0; p < 4; p++) {
                mn[p] = seg[t + 8 + 2 * p + half_];
                vn[p] = *(const uint4*)(hw + (size_t)mn[p].x * D + cl);
            }
        }
#pragma unroll
        for (int p = 0; p < 4; p++) {
            float w = __uint_as_float(mcur[p].y);
            float2 f0 = __half22float2(*(__half2*)&vcur[p].x);
            float2 f1 = __half22float2(*(__half2*)&vcur[p].y);
            float2 f2 = __half22float2(*(__half2*)&vcur[p].z);
            float2 f3 = __half22float2(*(__half2*)&vcur[p].w);
            acc[0] += w * f0.x; acc[1] += w * f0.y;
            acc[2] += w * f1.x; acc[3] += w * f1.y;
            acc[4] += w * f2.x; acc[5] += w * f2.y;
            acc[6] += w * f3.x; acc[7] += w * f3.y;
        }
        if (more) {
#pragma unroll
            for (int p = 0; p < 4; p++) { mcur[p] = mn[p]; vcur[p] = vn[p]; }
        }
    }

#pragma unroll
    for (int i = 0; i < 8; i++) acc[i] += __shfl_xor_sync(0xffffffffu, acc[i], 16);
#pragma unroll
    for (int o = 16; o; o >>= 1) dsum += __shfl_xor_sync(0xffffffffu, dsum, o);
    if (lane == 0) sdsum[r][sub] = dsum;

    // sub 1 stages its partial row; sub 0 merges + normalizes + writes
    if (sub == 1 && lane < 16) {
#pragma unroll
        for (int i = 0; i < 8; i++) sacc[r][cl + i] = acc[i];
    }
    __syncthreads();
    if (sub == 0 && lane < 16) {
        float dsumT = sdsum[r][0] + sdsum[r][1];
        float inv = 1.f / ((float)V + dsumT);
        float4 Sa = *(const float4*)(g_S + cl);
        float4 Sb = *(const float4*)(g_S + cl + 4);
        float4 o0, o1;
        o0.x = (Sa.x + acc[0] + sacc[r][cl + 0]) * inv;
        o0.y = (Sa.y + acc[1] + sacc[r][cl + 1]) * inv;
        o0.z = (Sa.z + acc[2] + sacc[r][cl + 2]) * inv;
        o0.w = (Sa.w + acc[3] + sacc[r][cl + 3]) * inv;
        o1.x = (Sb.x + acc[4] + sacc[r][cl + 4]) * inv;
        o1.y = (Sb.y + acc[5] + sacc[r][cl + 5]) * inv;
        o1.z = (Sb.z + acc[6] + sacc[r][cl + 6]) * inv;
        o1.w = (Sb.w + acc[7] + sacc[r][cl + 7]) * inv;
        *(float4*)(out + (size_t)row * D + cl) = o0;
        *(float4*)(out + (size_t)row * D + cl + 4) = o1;
    }
}

// ----------------------------------------------------------------------------
extern "C" void kernel_launch(void* const* d_in, const int* in_sizes, int n_in,
                              void* d_out, int out_size) {
    const float* h   = (const float*)d_in[0];
    const int*   ei  = (const int*)d_in[1];
    const float* Wm  = (const float*)d_in[2];
    const float* att = (const float*)d_in[3];
    float* out = (float*)d_out;

    cudaFuncSetAttribute(k_gemm, cudaFuncAttributeMaxDynamicSharedMemorySize,
                         GEMM_SMEM_BYTES);
    k_prep<<<16, 256>>>(Wm, ei);
    k_gemm<<<GB, 256, GEMM_SMEM_BYTES>>>(h, att);
    k_scatter<<<E / 256, 256>>>(ei);
    k_row<<<V / RPB, 256>>>(out);
}

// round 17
// speedup vs baseline: 1.1732x; 1.1732x over previous
#include <cuda_runtime.h>
#include <cuda_fp16.h>
#include <mma.h>
using namespace nvcuda;

#define V 8192
#define E 262144
#define D 128
#define SLOTS 128           // hash slots per row (power of 2)
#define GB 256              // gemm grid: V / 32 rows per block

// padded smem strides (bank-conflict-free for LDSM: stride mod 128B == 16B)
#define WS 136              // half stride for W/A tiles  (272 B)
#define CS 132              // float stride for C tile    (528 B)

// dynamic smem: Whi+Wlo (2*128*136*2) + Ahi+Alo (2*32*136*2) + C (32*132*4)
#define GEMM_SMEM_BYTES (2*128*WS*2 + 2*32*WS*2 + 32*CS*4)

// ---------------- scratch (device globals; no allocations allowed) ----------
__device__ __half             g_hwh[V * D];      // hw in fp16 (2 MB, L2-resident)
__device__ __half             g_Whi[D * D];      // W hi split (pre-converted once)
__device__ __half             g_Wlo[D * D];      // W lo split
__device__ float              g_s1[V];           // hw[v] . att[:128]  (exact fp32)
__device__ float              g_s2[V];           // hw[v] . att[128:]
__device__ float              g_Spart[GB * D];   // per-block colsum partials
__device__ float              g_S[D];            // reduced colsum of hw
__device__ unsigned           g_ew32[(size_t)V * SLOTS]; // (idx+1)<<13 | dst
__device__ int                g_is64;            // edge_index dtype flag

// =================== K0: W fp16-split (once) + dtype detection ===============
__global__ void k_prep(const float* __restrict__ Wm, const int* __restrict__ e32) {
    int tid = threadIdx.x;
    if (blockIdx.x == 0) {
        __shared__ int flag;
        if (tid == 0) flag = 0;
        __syncthreads();
        if (e32[2 * tid + 1] != 0) atomicExch(&flag, 1);
        __syncthreads();
        if (tid == 0) g_is64 = (flag == 0) ? 1 : 0;
    }
    int i4 = blockIdx.x * 256 + tid;              // 0..4095
    float4 v = ((const float4*)Wm)[i4];
    __half hx = __float2half_rn(v.x), hy = __float2half_rn(v.y);
    __half hz = __float2half_rn(v.z), hw_ = __float2half_rn(v.w);
    __half2 ph0 = __halves2half2(hx, hy), ph1 = __halves2half2(hz, hw_);
    __half lx = __float2half_rn(v.x - __half2float(hx));
    __half ly = __float2half_rn(v.y - __half2float(hy));
    __half lz = __float2half_rn(v.z - __half2float(hz));
    __half lw = __float2half_rn(v.w - __half2float(hw_));
    __half2 pl0 = __halves2half2(lx, ly), pl1 = __halves2half2(lz, lw);
    uint2 uh, ul;
    uh.x = *(unsigned*)&ph0; uh.y = *(unsigned*)&ph1;
    ul.x = *(unsigned*)&pl0; ul.y = *(unsigned*)&pl1;
    *(uint2*)(g_Whi + (size_t)i4 * 4) = uh;
    *(uint2*)(g_Wlo + (size_t)i4 * 4) = ul;
}

// =================== K1: tensor-core GEMM hw = h @ W^T (fp16-split, smem) ====
__global__ void __launch_bounds__(256) k_gemm(const float* __restrict__ h,
                                              const float* __restrict__ att) {
    extern __shared__ char dynsmem[];
    __half* sWhi = (__half*)dynsmem;              // [128][WS]  W[col][k]
    __half* sWlo = sWhi + 128 * WS;
    __half* sAhi = sWlo + 128 * WS;               // [32][WS]
    __half* sAlo = sAhi + 32 * WS;
    float*  sC   = (float*)(sAlo + 32 * WS);      // [32][CS] fp32 result

    int tid = threadIdx.x;
    int warpId = tid >> 5, lane = tid & 31;
    int row0 = blockIdx.x * 32;

    // ---- copy pre-split W into padded smem: 2048 uint4 per array, 8/thread
    const uint4* Wh4 = (const uint4*)g_Whi;
    const uint4* Wl4 = (const uint4*)g_Wlo;
#pragma unroll
    for (int j = 0; j < 8; j++) {
        int i = tid + j * 256;                    // 0..2047
        int row = i >> 4, c8 = (i & 15) * 8;
        *(uint4*)(sWhi + row * WS + c8) = Wh4[i];
        *(uint4*)(sWlo + row * WS + c8) = Wl4[i];
    }
    // ---- convert A (32 rows x 128 = 1024 float4): 4 per thread ----
#pragma unroll
    for (int j = 0; j < 4; j++) {
        int i4 = tid + j * 256;
        int row = i4 >> 5, c4 = (i4 & 31) * 4;
        float4 v = *(const float4*)(h + (size_t)row0 * D + (size_t)i4 * 4);
        __half hx = __float2half_rn(v.x), hy = __float2half_rn(v.y);
        __half hz = __float2half_rn(v.z), hw_ = __float2half_rn(v.w);
        __half2 ph0 = __halves2half2(hx, hy), ph1 = __halves2half2(hz, hw_);
        __half lx = __float2half_rn(v.x - __half2float(hx));
        __half ly = __float2half_rn(v.y - __half2float(hy));
        __half lz = __float2half_rn(v.z - __half2float(hz));
        __half lw = __float2half_rn(v.w - __half2float(hw_));
        __half2 pl0 = __halves2half2(lx, ly), pl1 = __halves2half2(lz, lw);
        uint2 uh, ul;
        uh.x = *(unsigned*)&ph0; uh.y = *(unsigned*)&ph1;
        ul.x = *(unsigned*)&pl0; ul.y = *(unsigned*)&pl1;
        *(uint2*)(sAhi + row * WS + c4) = uh;
        *(uint2*)(sAlo + row * WS + c4) = ul;
    }
    __syncthreads();

    // ---- wmma: warp w -> col-tile w; row-tiles 0,1 ----
    int ct = warpId;
#pragma unroll
    for (int rt = 0; rt < 2; rt++) {
        wmma::fragment<wmma::accumulator, 16, 16, 16, float> acc;
        wmma::fill_fragment(acc, 0.f);
#pragma unroll
        for (int k0 = 0; k0 < 8; k0++) {
            wmma::fragment<wmma::matrix_a, 16, 16, 16, __half, wmma::row_major> ahi, alo;
            wmma::load_matrix_sync(ahi, sAhi + rt * 16 * WS + k0 * 16, WS);
            wmma::load_matrix_sync(alo, sAlo + rt * 16 * WS + k0 * 16, WS);
            wmma::fragment<wmma::matrix_b, 16, 16, 16, __half, wmma::col_major> bhi, blo;
            wmma::load_matrix_sync(bhi, sWhi + ct * 16 * WS + k0 * 16, WS);
            wmma::load_matrix_sync(blo, sWlo + ct * 16 * WS + k0 * 16, WS);
            wmma::mma_sync(acc, ahi, bhi, acc);
            wmma::mma_sync(acc, ahi, blo, acc);
            wmma::mma_sync(acc, alo, bhi, acc);
        }
        wmma::store_matrix_sync(sC + rt * 16 * CS + ct * 16, acc, CS, wmma::mem_row_major);
    }
    __syncthreads();

    // ---- epilogue (all from fp32 sC) ----
#pragma unroll
    for (int j = 0; j < 4; j++) {
        int i4 = tid + j * 256;
        int row = i4 >> 5, off = (i4 & 31) * 4;
        float4 v = *(const float4*)(sC + row * CS + off);
        __half2 q0 = __floats2half2_rn(v.x, v.y);
        __half2 q1 = __floats2half2_rn(v.z, v.w);
        uint2 u;
        u.x = *(unsigned*)&q0; u.y = *(unsigned*)&q1;
        *(uint2*)(g_hwh + (size_t)(row0 + row) * D + off) = u;
    }
    // s1/s2: warp w owns rows 4w..4w+3; lane dots 4 cols, shfl-reduce (exact fp32)
    {
        float4 a1 = *(const float4*)(att + lane * 4);
        float4 a2 = *(const float4*)(att + D + lane * 4);
#pragma unroll
        for (int r = 0; r < 4; r++) {
            int row = warpId * 4 + r;
            float4 cv = *(const float4*)(sC + row * CS + lane * 4);
            float s1 = cv.x * a1.x + cv.y * a1.y + cv.z * a1.z + cv.w * a1.w;
            float s2 = cv.x * a2.x + cv.y * a2.y + cv.z * a2.z + cv.w * a2.w;
#pragma unroll
            for (int o = 16; o; o >>= 1) {
                s1 += __shfl_xor_sync(0xffffffffu, s1, o);
                s2 += __shfl_xor_sync(0xffffffffu, s2, o);
            }
            if (lane == 0) { g_s1[row0 + row] = s1; g_s2[row0 + row] = s2; }
        }
    }
    // colsum partial: threads 0..127, column tid over 32 rows (conflict-free)
    if (tid < D) {
        float s = 0.f;
#pragma unroll 8
        for (int r = 0; r < 32; r++) s += sC[r * CS + tid];
        g_Spart[blockIdx.x * D + tid] = s;
    }
}

// =================== K2: hash insert only (32-bit; dedup by atomicMax) =======
// Record: bits[0:13)=dst, [13:32)=edge_idx+1. Max idx wins = last-write-wins.
__global__ void k_scatter(const int* __restrict__ e32) {
    // block 0: reduce colsum partials -> g_S (k_row reads it later)
    if (blockIdx.x == 0 && threadIdx.x < D) {
        float s = 0.f;
#pragma unroll 16
        for (int b = 0; b < GB; b++) s += g_Spart[b * D + threadIdx.x];
        g_S[threadIdx.x] = s;
    }
    int e = blockIdx.x * blockDim.x + threadIdx.x;
    if (e >= E) return;
    int src, dst;
    if (g_is64) {
        src = ((const int2*)e32)[e].x;
        dst = ((const int2*)e32)[E + e].x;
    } else {
        src = e32[e];
        dst = e32[E + e];
    }
    unsigned rec = ((unsigned)(e + 1) << 13) | (unsigned)dst;
    unsigned slot = ((unsigned)dst * 2654435761u) >> 25;   // 7-bit hash
    unsigned* tab = g_ew32 + (size_t)src * SLOTS;
    for (int probe = 0; probe < SLOTS; probe++) {
        unsigned old = atomicCAS(&tab[slot], 0u, rec);
        if (old == 0u) break;                              // claimed empty slot
        if ((old & 0x1FFFu) == (unsigned)dst) {
            atomicMax(&tab[slot], rec);                    // last-write-wins
            break;
        }
        slot = (slot + 1) & (SLOTS - 1);
    }
}

// =================== K3: slot scan + 2-deep pipelined gather =================
// One warp per row (R15 geometry). Value prefetch 2 groups deep (8 LDG.128
// in flight per warp); metadata re-read from shared at consume (keeps regs low).
__global__ void __launch_bounds__(256, 4) k_row(float* __restrict__ out) {
    __shared__ uint2 sm[8][SLOTS];     // {dst, float bits of w}
    int wid = threadIdx.x >> 5, lane = threadIdx.x & 31;
    int row = blockIdx.x * 8 + wid;
    unsigned* tab = g_ew32 + (size_t)row * SLOTS;
    float s1row = g_s1[row];

    float dsum = 0.f;
    int cnt = 0;
#pragma unroll
    for (int rnd = 0; rnd < SLOTS / 32; rnd++) {
        int s = rnd * 32 + lane;
        unsigned v = tab[s];
        tab[s] = 0u;                                     // replay-safe re-zero
        unsigned mask = __ballot_sync(0xffffffffu, v != 0u);
        if (v != 0u) {
            int pos = cnt + __popc(mask & ((1u << lane) - 1u));
            unsigned dst = v & 0x1FFFu;
            float a = s1row + g_s2[dst];
            a = a > 0.f ? a : 0.2f * a;                  // LeakyReLU(0.2)
            float w = expm1f(a);                         // exp(a) - 1 (fp32)
            sm[wid][pos] = make_uint2(dst, __float_as_uint(w));
            dsum += w;
        }
        cnt += __popc(mask);
    }
    int dpad = (cnt + 7) & ~7;
    for (int t = cnt + lane; t < dpad; t += 32)
        sm[wid][t] = make_uint2(0u, 0u);                 // harmless pad (w=0)
    __syncwarp();

    float acc[8];
#pragma unroll
    for (int i = 0; i < 8; i++) acc[i] = 0.f;
    int half_ = lane >> 4;
    int cl = (lane & 15) * 8;
    const __half* hw = g_hwh;

    uint4 vb0[4], vb1[4];

#define ISSUE(buf, base) do {                                              \
        _Pragma("unroll")                                                  \
        for (int p = 0; p < 4; p++) {                                      \
            unsigned d_ = sm[wid][(base) + 2 * p + half_].x;               \
            buf[p] = *(const uint4*)(hw + (size_t)d_ * D + cl);            \
        }                                                                  \
    } while (0)

#define CONSUME(buf, base) do {                                            \
        _Pragma("unroll")                                                  \
        for (int p = 0; p < 4; p++) {                                      \
            float w_ = __uint_as_float(sm[wid][(base) + 2 * p + half_].y); \
            float2 f0 = __half22float2(*(__half2*)&buf[p].x);              \
            float2 f1 = __half22float2(*(__half2*)&buf[p].y);              \
            float2 f2 = __half22float2(*(__half2*)&buf[p].z);              \
            float2 f3 = __half22float2(*(__half2*)&buf[p].w);              \
            acc[0] += w_ * f0.x; acc[1] += w_ * f0.y;                      \
            acc[2] += w_ * f1.x; acc[3] += w_ * f1.y;                      \
            acc[4] += w_ * f2.x; acc[5] += w_ * f2.y;                      \
            acc[6] += w_ * f3.x; acc[7] += w_ * f3.y;                      \
        }                                                                  \
    } while (0)

    if (dpad > 0) ISSUE(vb0, 0);
    if (dpad > 8) ISSUE(vb1, 8);
    int t = 0;
    while (t < dpad) {
        CONSUME(vb0, t);
        if (t + 16 < dpad) ISSUE(vb0, t + 16);
        t += 8;
        if (t >= dpad) break;
        CONSUME(vb1, t);
        if (t + 16 < dpad) ISSUE(vb1, t + 16);
        t += 8;
    }
#undef ISSUE
#undef CONSUME

#pragma unroll
    for (int i = 0; i < 8; i++) acc[i] += __shfl_xor_sync(0xffffffffu, acc[i], 16);
#pragma unroll
    for (int o = 16; o; o >>= 1) dsum += __shfl_xor_sync(0xffffffffu, dsum, o);

    float inv = 1.f / ((float)V + dsum);
    if (lane < 16) {
        float4 Sa = *(const float4*)(g_S + cl);
        float4 Sb = *(const float4*)(g_S + cl + 4);
        float4 o0, o1;
        o0.x = (Sa.x + acc[0]) * inv; o0.y = (Sa.y + acc[1]) * inv;
        o0.z = (Sa.z + acc[2]) * inv; o0.w = (Sa.w + acc[3]) * inv;
        o1.x = (Sb.x + acc[4]) * inv; o1.y = (Sb.y + acc[5]) * inv;
        o1.z = (Sb.z + acc[6]) * inv; o1.w = (Sb.w + acc[7]) * inv;
        *(float4*)(out + (size_t)row * D + cl) = o0;
        *(float4*)(out + (size_t)row * D + cl + 4) = o1;
    }
}

// ----------------------------------------------------------------------------
extern "C" void kernel_launch(void* const* d_in, const int* in_sizes, int n_in,
                              void* d_out, int out_size) {
    const float* h   = (const float*)d_in[0];
    const int*   ei  = (const int*)d_in[1];
    const float* Wm  = (const float*)d_in[2];
    const float* att = (const float*)d_in[3];
    float* out = (float*)d_out;

    cudaFuncSetAttribute(k_gemm, cudaFuncAttributeMaxDynamicSharedMemorySize,
                         GEMM_SMEM_BYTES);
    k_prep<<<16, 256>>>(Wm, ei);
    k_gemm<<<GB, 256, GEMM_SMEM_BYTES>>>(h, att);
    k_scatter<<<E / 256, 256>>>(ei);
    k_row<<<V / 8, 256>>>(out);
}